// round 6
// baseline (speedup 1.0000x reference)
#include <cuda_runtime.h>
#include <math.h>

#define NVEC 131072
#define DIMS 64
#define KCODES 256
#define NBLK 148
#define NTHR 512

// Output packing (tuple flattened, fp32):
// loss(1), out(32*64*64*64), perplexity(1), idx(131072), new_emb_w(16384), new_cs(256), new_ema_w(16384)
#define OFF_LOSS 0
#define OFF_OUT  1
#define OFF_PERP 8388609
#define OFF_IDX  8388610
#define OFF_EMBW 8519682
#define OFF_CS   8536066
#define OFF_EMAW 8536322

// scratch: [0,16384) dw, [16384,16640) counts, [16640] loss accumulator
// Zero-initialized at module load; vq_finalize re-zeros after consuming, so
// every graph replay (and the correctness call) sees zeros. No zero kernel.
__device__ float g_scr[16641];

typedef unsigned long long ull;

__device__ __forceinline__ ull ffma2(ull a, ull b, ull c) {
    ull d;
    asm("fma.rn.f32x2 %0, %1, %2, %3;" : "=l"(d) : "l"(a), "l"(b), "l"(c));
    return d;
}
__device__ __forceinline__ ull pack2(float a, float b) {
    ull r;
    asm("mov.b64 %0, {%1, %2};" : "=l"(r) : "f"(a), "f"(b));
    return r;
}
__device__ __forceinline__ float lo32(ull v) { return __uint_as_float((unsigned)v); }
__device__ __forceinline__ float hi32(ull v) { return __uint_as_float((unsigned)(v >> 32)); }

// ---------------------------------------------------------------------------
// Kernel 1: distances + argmin + quantized output + loss + dw/count partials
// ---------------------------------------------------------------------------
__global__ void __launch_bounds__(NTHR, 1)
vq_main(const float* __restrict__ in, const float* __restrict__ emb,
        float* __restrict__ dout) {
    extern __shared__ float sm[];
    float* s_e   = sm;             // 16384: natural layout codebook (broadcast dot reads)
    float* s_eg  = sm + 16384;     // 16384: rotation-swizzled copy for per-lane gather
    float* s_h   = sm + 32768;     // 256:   0.5*||e_k||^2
    float* s_red = sm + 33024;     // 16:    loss reduction
    const ull* s_eu = (const ull*)s_e;

    const int tid = threadIdx.x;
    const int lane = tid & 31;

    for (int i = tid; i < 16384; i += NTHR) {
        float v = emb[i];
        int k = i >> 6, c = i & 63;
        s_e[i] = v;
        s_eg[(k << 6) + ((c + k) & 63)] = v;
    }
    if (tid < KCODES) {
        float s = 0.f;
        const float* er = emb + (tid << 6);
#pragma unroll
        for (int c = 0; c < 64; c++) s += er[c] * er[c];
        s_h[tid] = 0.5f * s;
    }
    __syncthreads();

    float lossacc = 0.f;

    // All strides/bases are multiples of 32 => warps stay convergent.
    for (int n = blockIdx.x * NTHR + tid; n < NVEC; n += NBLK * NTHR) {
        int b = n >> 12, hw = n & 4095;
        const float* xp = in + b * 262144 + hw;

        // Load x (stride 4096 over channels), packed as {x[2j], x[2j+1]}.
        ull x2[32];
#pragma unroll
        for (int j = 0; j < 32; j++)
            x2[j] = pack2(xp[(2 * j) << 12], xp[(2 * j + 1) << 12]);

        // argmin_k (0.5*||e_k||^2 - x.e_k) == argmin ||x-e_k||^2.
        // 8 codes per group, one f32x2 accumulator per code (pairs of dims),
        // horizontal add at group end.
        float best = 3.402823466e+38f;
        float best2 = 3.402823466e+38f;
        int bestk = 0;
#pragma unroll 1
        for (int kb = 0; kb < KCODES; kb += 8) {
            const ull* e0 = s_eu + (kb << 5);
            ull a0 = 0, a1 = 0, a2 = 0, a3 = 0, a4 = 0, a5 = 0, a6 = 0, a7 = 0;
#pragma unroll
            for (int j = 0; j < 32; j += 2) {
                ulonglong2 q0 = *(const ulonglong2*)(e0 + j);
                ulonglong2 q1 = *(const ulonglong2*)(e0 + 32 + j);
                ulonglong2 q2 = *(const ulonglong2*)(e0 + 64 + j);
                ulonglong2 q3 = *(const ulonglong2*)(e0 + 96 + j);
                ulonglong2 q4 = *(const ulonglong2*)(e0 + 128 + j);
                ulonglong2 q5 = *(const ulonglong2*)(e0 + 160 + j);
                ulonglong2 q6 = *(const ulonglong2*)(e0 + 192 + j);
                ulonglong2 q7 = *(const ulonglong2*)(e0 + 224 + j);
                a0 = ffma2(x2[j], q0.x, a0); a0 = ffma2(x2[j + 1], q0.y, a0);
                a1 = ffma2(x2[j], q1.x, a1); a1 = ffma2(x2[j + 1], q1.y, a1);
                a2 = ffma2(x2[j], q2.x, a2); a2 = ffma2(x2[j + 1], q2.y, a2);
                a3 = ffma2(x2[j], q3.x, a3); a3 = ffma2(x2[j + 1], q3.y, a3);
                a4 = ffma2(x2[j], q4.x, a4); a4 = ffma2(x2[j + 1], q4.y, a4);
                a5 = ffma2(x2[j], q5.x, a5); a5 = ffma2(x2[j + 1], q5.y, a5);
                a6 = ffma2(x2[j], q6.x, a6); a6 = ffma2(x2[j + 1], q6.y, a6);
                a7 = ffma2(x2[j], q7.x, a7); a7 = ffma2(x2[j + 1], q7.y, a7);
            }
            float sc;
#define VQ_CAND(KOFF, ACC)                                                  \
            sc = s_h[kb + KOFF] - (lo32(ACC) + hi32(ACC));                  \
            if (sc < best) { best2 = best; best = sc; bestk = kb + KOFF; }  \
            else if (sc < best2) { best2 = sc; }
            VQ_CAND(0, a0) VQ_CAND(1, a1) VQ_CAND(2, a2) VQ_CAND(3, a3)
            VQ_CAND(4, a4) VQ_CAND(5, a5) VQ_CAND(6, a6) VQ_CAND(7, a7)
#undef VQ_CAND
        }

        // Near-tie fixup: fp32 score noise ~2e-5; gap < 4e-3 (200x margin) =>
        // exact fp64 recompute, warp-cooperative (lane owns 8 codes; swizzled
        // LDS => conflict-free). Tie band 3e-6 -> lower index (argmin rule).
        unsigned fmask = __ballot_sync(0xffffffffu, (best2 - best) < 4e-3f);
        while (fmask) {
            int src = __ffs(fmask) - 1; fmask &= fmask - 1;
            int ns = n - lane + src;
            const float* xs = in + (ns >> 12) * 262144 + (ns & 4095);
            double bd = 1e300; int bk = 0;
#pragma unroll 1
            for (int kk = 0; kk < 8; kk++) {
                int k = kk * 32 + lane;
                const float* er = s_eg + (k << 6);
                double sA = 0.0, sB = 0.0;
#pragma unroll
                for (int c = 0; c < 64; c += 2) {
                    double d0 = (double)xs[c << 12] - (double)er[(c + k) & 63];
                    double d1 = (double)xs[(c + 1) << 12] - (double)er[(c + 1 + k) & 63];
                    sA += d0 * d0; sB += d1 * d1;
                }
                double s = sA + sB;
                if (s < bd - 3e-6 || (s < bd + 3e-6 && k < bk)) { bd = s; bk = k; }
            }
#pragma unroll
            for (int o = 16; o; o >>= 1) {
                double od = __shfl_xor_sync(0xffffffffu, bd, o);
                int ok = __shfl_xor_sync(0xffffffffu, bk, o);
                if (od < bd - 3e-6 || (od < bd + 3e-6 && ok < bk)) { bd = od; bk = ok; }
            }
            if (lane == src) bestk = bk;
        }

        // Straight-through output fl(x + fl(q-x)) bit-faithfully, loss, and
        // dw/count via global REDG (fire-and-forget, no MIO crossbar cost).
        float* op = dout + OFF_OUT + b * 262144 + hw;
        int kb64 = bestk << 6;
#pragma unroll
        for (int c = 0; c < 64; c++) {
            float e = s_eg[kb64 + ((c + bestk) & 63)];
            float xv = (c & 1) ? hi32(x2[c >> 1]) : lo32(x2[c >> 1]);
            float df = e - xv;
            lossacc += df * df;
            op[c << 12] = xv + df;
            atomicAdd(&g_scr[kb64 + c], xv);
        }
        dout[OFF_IDX + n] = (float)bestk;
        atomicAdd(&g_scr[16384 + bestk], 1.0f);
    }

    // Loss: warp reduce -> shared -> one atomic per block.
#pragma unroll
    for (int o = 16; o; o >>= 1) lossacc += __shfl_xor_sync(0xffffffffu, lossacc, o);
    if (lane == 0) s_red[tid >> 5] = lossacc;
    __syncthreads();
    if (tid == 0) {
        float s = 0.f;
        for (int w = 0; w < NTHR / 32; w++) s += s_red[w];
        atomicAdd(&g_scr[16640], s);
    }
}

// ---------------------------------------------------------------------------
// Kernel 2: finalize EMA updates, perplexity, loss; re-zero scratch.
// ---------------------------------------------------------------------------
__global__ void vq_finalize(const float* __restrict__ cs_in,
                            const float* __restrict__ emaw_in,
                            float* __restrict__ dout) {
    __shared__ float s_cs[256];
    __shared__ float s_red[8];
    int t = threadIdx.x;
    int lane = t & 31, w = t >> 5;

    float cnt = g_scr[16384 + t];
    g_scr[16384 + t] = 0.f;  // self-clean for next replay (same thread rezeros)
    float ncs = cs_in[t] * 0.99f + 0.01f * cnt;

    // n = sum(new_cs)
    float v = ncs;
#pragma unroll
    for (int o = 16; o; o >>= 1) v += __shfl_xor_sync(0xffffffffu, v, o);
    if (lane == 0) s_red[w] = v;
    __syncthreads();
    float nsum = 0.f;
#pragma unroll
    for (int j = 0; j < 8; j++) nsum += s_red[j];

    float csf = (ncs + 1e-5f) / (nsum + 256.f * 1e-5f) * nsum;
    s_cs[t] = csf;
    dout[OFF_CS + t] = csf;

    // perplexity
    float avg = cnt * (1.0f / (float)NVEC);
    float term = avg * logf(avg + 1e-10f);
    float e = term;
#pragma unroll
    for (int o = 16; o; o >>= 1) e += __shfl_xor_sync(0xffffffffu, e, o);
    __syncthreads();  // protect s_red reuse
    if (lane == 0) s_red[w] = e;
    __syncthreads();
    if (t == 0) {
        float es = 0.f;
        for (int j = 0; j < 8; j++) es += s_red[j];
        dout[OFF_PERP] = expf(-es);
        dout[OFF_LOSS] = 0.25f * g_scr[16640] * (1.0f / 8388608.0f);
        g_scr[16640] = 0.f;
    }

    // new_ema_w and new_emb_w; zero dw scratch after reading (same thread).
    for (int i = t; i < 16384; i += 256) {
        float ew = emaw_in[i] * 0.99f + 0.01f * g_scr[i];
        g_scr[i] = 0.f;
        dout[OFF_EMAW + i] = ew;
        dout[OFF_EMBW + i] = ew / s_cs[i >> 6];
    }
}

// ---------------------------------------------------------------------------
extern "C" void kernel_launch(void* const* d_in, const int* in_sizes, int n_in,
                              void* d_out, int out_size) {
    const float* in   = (const float*)d_in[0];
    const float* emb  = (const float*)d_in[1];
    const float* cs   = (const float*)d_in[2];
    const float* emaw = (const float*)d_in[3];
    float* dout = (float*)d_out;

    const int smem = 33040 * 4;  // 132160 B dynamic shared
    cudaFuncSetAttribute(vq_main, cudaFuncAttributeMaxDynamicSharedMemorySize, smem);

    vq_main<<<NBLK, NTHR, smem>>>(in, emb, dout);
    vq_finalize<<<1, 256>>>(cs, emaw, dout);
}

// round 8
// speedup vs baseline: 1.9319x; 1.9319x over previous
#include <cuda_runtime.h>
#include <math.h>

#define NVEC 131072
#define DIMS 64
#define KCODES 256
#define NBLK 148
#define NTHR 512

// Output packing (tuple flattened, fp32):
// loss(1), out(32*64*64*64), perplexity(1), idx(131072), new_emb_w(16384), new_cs(256), new_ema_w(16384)
#define OFF_LOSS 0
#define OFF_OUT  1
#define OFF_PERP 8388609
#define OFF_IDX  8388610
#define OFF_EMBW 8519682
#define OFF_CS   8536066
#define OFF_EMAW 8536322

// scratch: [0,16384) dw, [16384,16640) counts, [16640] loss accumulator
// Zero at module load; vq_finalize re-zeros after consuming => every graph
// replay (and the correctness call) sees zeros.
__device__ float g_scr[16641];
__device__ float g_pad_sink;

typedef unsigned long long ull;

__device__ __forceinline__ ull ffma2(ull a, ull b, ull c) {
    ull d;
    asm("fma.rn.f32x2 %0, %1, %2, %3;" : "=l"(d) : "l"(a), "l"(b), "l"(c));
    return d;
}
__device__ __forceinline__ ull pack2(float a, float b) {
    ull r;
    asm("mov.b64 %0, {%1, %2};" : "=l"(r) : "f"(a), "f"(b));
    return r;
}
__device__ __forceinline__ float lo32(ull v) { return __uint_as_float((unsigned)v); }
__device__ __forceinline__ float hi32(ull v) { return __uint_as_float((unsigned)(v >> 32)); }

// Pad kernel: makes each kernel_launch 4 launches with vq_main at position 2,
// so ncu's fixed "-s 5 -c 1" (global launch #6) captures vq_main.
__global__ void vq_pad() { if (threadIdx.x == 0) g_pad_sink = 0.f; }

// ---------------------------------------------------------------------------
// Kernel 1: distances + argmin + ST output + loss + dw/count partials
// ---------------------------------------------------------------------------
__global__ void __launch_bounds__(NTHR, 1)
vq_main(const float* __restrict__ in, const float* __restrict__ emb,
        float* __restrict__ dout) {
    extern __shared__ float sm[];
    float* s_e   = sm;             // 16384: natural codebook (broadcast reads)
    float* s_eg  = sm + 16384;     // 16384: rotation-swizzled copy (per-lane gather)
    float* s_dw  = sm + 32768;     // 16640: dw accumulator, PADDED stride 65
    float* s_h   = sm + 49408;     // 256:   0.5*||e_k||^2
    float* s_cnt = sm + 49664;     // 256:   per-block counts
    float* s_red = sm + 49920;     // 16:    loss reduction
    const ull* s_eu = (const ull*)s_e;

    const int tid = threadIdx.x;
    const int lane = tid & 31;

    for (int i = tid; i < 16640; i += NTHR) s_dw[i] = 0.f;
    for (int i = tid; i < 16384; i += NTHR) {
        float v = emb[i];
        int k = i >> 6, c = i & 63;
        s_e[i] = v;
        s_eg[(k << 6) + ((c + k) & 63)] = v;
    }
    if (tid < KCODES) {
        float s = 0.f;
        const float* er = emb + (tid << 6);
#pragma unroll
        for (int c = 0; c < 64; c++) s += er[c] * er[c];
        s_h[tid] = 0.5f * s;
        s_cnt[tid] = 0.f;
    }
    __syncthreads();

    float lossacc = 0.f;

    // All strides/bases are multiples of 32 => warps stay convergent.
    for (int n = blockIdx.x * NTHR + tid; n < NVEC; n += NBLK * NTHR) {
        int b = n >> 12, hw = n & 4095;
        const float* xp = in + b * 262144 + hw;

        // x packed as {x[2j], x[2j+1]}. ALL indices below are compile-time
        // constants so x2 stays in registers (no local-memory demotion).
        ull x2[32];
#pragma unroll
        for (int j = 0; j < 32; j++)
            x2[j] = pack2(xp[(2 * j) << 12], xp[(2 * j + 1) << 12]);

        // argmin_k (0.5*||e_k||^2 - x.e_k) == argmin ||x-e_k||^2.
        float best = 3.402823466e+38f;
        float best2 = 3.402823466e+38f;
        int bestk = 0;
#pragma unroll 1
        for (int kb = 0; kb < KCODES; kb += 8) {
            const ull* e0 = s_eu + (kb << 5);
            ull a0 = 0, a1 = 0, a2 = 0, a3 = 0, a4 = 0, a5 = 0, a6 = 0, a7 = 0;
#pragma unroll
            for (int j = 0; j < 32; j += 2) {
                ulonglong2 q0 = *(const ulonglong2*)(e0 + j);
                ulonglong2 q1 = *(const ulonglong2*)(e0 + 32 + j);
                ulonglong2 q2 = *(const ulonglong2*)(e0 + 64 + j);
                ulonglong2 q3 = *(const ulonglong2*)(e0 + 96 + j);
                ulonglong2 q4 = *(const ulonglong2*)(e0 + 128 + j);
                ulonglong2 q5 = *(const ulonglong2*)(e0 + 160 + j);
                ulonglong2 q6 = *(const ulonglong2*)(e0 + 192 + j);
                ulonglong2 q7 = *(const ulonglong2*)(e0 + 224 + j);
                a0 = ffma2(x2[j], q0.x, a0); a0 = ffma2(x2[j + 1], q0.y, a0);
                a1 = ffma2(x2[j], q1.x, a1); a1 = ffma2(x2[j + 1], q1.y, a1);
                a2 = ffma2(x2[j], q2.x, a2); a2 = ffma2(x2[j + 1], q2.y, a2);
                a3 = ffma2(x2[j], q3.x, a3); a3 = ffma2(x2[j + 1], q3.y, a3);
                a4 = ffma2(x2[j], q4.x, a4); a4 = ffma2(x2[j + 1], q4.y, a4);
                a5 = ffma2(x2[j], q5.x, a5); a5 = ffma2(x2[j + 1], q5.y, a5);
                a6 = ffma2(x2[j], q6.x, a6); a6 = ffma2(x2[j + 1], q6.y, a6);
                a7 = ffma2(x2[j], q7.x, a7); a7 = ffma2(x2[j + 1], q7.y, a7);
            }
            float sc;
#define VQ_CAND(KOFF, ACC)                                                  \
            sc = s_h[kb + KOFF] - (lo32(ACC) + hi32(ACC));                  \
            if (sc < best) { best2 = best; best = sc; bestk = kb + KOFF; }  \
            else if (sc < best2) { best2 = sc; }
            VQ_CAND(0, a0) VQ_CAND(1, a1) VQ_CAND(2, a2) VQ_CAND(3, a3)
            VQ_CAND(4, a4) VQ_CAND(5, a5) VQ_CAND(6, a6) VQ_CAND(7, a7)
#undef VQ_CAND
        }

        // Near-tie fixup: fp32 score noise ~2e-5; gap < 4e-3 (200x margin) =>
        // exact fp64 recompute, warp-cooperative (lane owns 8 codes; swizzled
        // LDS => conflict-free). Tie band 3e-6 -> lower index (argmin rule).
        unsigned fmask = __ballot_sync(0xffffffffu, (best2 - best) < 4e-3f);
        while (fmask) {
            int src = __ffs(fmask) - 1; fmask &= fmask - 1;
            int ns = n - lane + src;
            const float* xs = in + (ns >> 12) * 262144 + (ns & 4095);
            double bd = 1e300; int bk = 0;
#pragma unroll 1
            for (int kk = 0; kk < 8; kk++) {
                int k = kk * 32 + lane;
                const float* er = s_eg + (k << 6);
                double sA = 0.0, sB = 0.0;
#pragma unroll
                for (int c = 0; c < 64; c += 2) {
                    double d0 = (double)xs[c << 12] - (double)er[(c + k) & 63];
                    double d1 = (double)xs[(c + 1) << 12] - (double)er[(c + 1 + k) & 63];
                    sA += d0 * d0; sB += d1 * d1;
                }
                double s = sA + sB;
                if (s < bd - 3e-6 || (s < bd + 3e-6 && k < bk)) { bd = s; bk = k; }
            }
#pragma unroll
            for (int o = 16; o; o >>= 1) {
                double od = __shfl_xor_sync(0xffffffffu, bd, o);
                int ok = __shfl_xor_sync(0xffffffffu, bk, o);
                if (od < bd - 3e-6 || (od < bd + 3e-6 && ok < bk)) { bd = od; bk = ok; }
            }
            if (lane == src) bestk = bk;
        }

        // ST output fl(x + fl(q-x)) bit-faithfully + loss + dw/count.
        // dw rows padded to 65 floats: bank = (65*bestk + c) % 32 =
        // (bestk + c) % 32 -> lanes with distinct codes hit distinct banks;
        // x2 index (c>>1) is a compile-time constant (loop fully unrolled).
        float* op = dout + OFF_OUT + b * 262144 + hw;
        int kb64 = bestk << 6;
        float* dwrow = s_dw + bestk * 65;
#pragma unroll
        for (int c = 0; c < 64; c++) {
            float e = s_eg[kb64 + ((c + bestk) & 63)];
            float xv = (c & 1) ? hi32(x2[c >> 1]) : lo32(x2[c >> 1]);
            float df = e - xv;
            lossacc += df * df;
            op[c << 12] = xv + df;
            atomicAdd(dwrow + c, xv);
        }
        dout[OFF_IDX + n] = (float)bestk;
        atomicAdd(s_cnt + bestk, 1.0f);
    }
    __syncthreads();

    // Flush per-block partials (padded -> logical layout) to global scratch.
    for (int i = tid; i < 16384; i += NTHR)
        atomicAdd(&g_scr[i], s_dw[(i >> 6) * 65 + (i & 63)]);
    if (tid < KCODES) atomicAdd(&g_scr[16384 + tid], s_cnt[tid]);

    // Loss: warp reduce -> shared -> one atomic per block.
#pragma unroll
    for (int o = 16; o; o >>= 1) lossacc += __shfl_xor_sync(0xffffffffu, lossacc, o);
    if (lane == 0) s_red[tid >> 5] = lossacc;
    __syncthreads();
    if (tid == 0) {
        float s = 0.f;
        for (int w = 0; w < NTHR / 32; w++) s += s_red[w];
        atomicAdd(&g_scr[16640], s);
    }
}

// ---------------------------------------------------------------------------
// Kernel 2: finalize EMA updates, perplexity, loss; re-zero scratch.
// ---------------------------------------------------------------------------
__global__ void vq_finalize(const float* __restrict__ cs_in,
                            const float* __restrict__ emaw_in,
                            float* __restrict__ dout) {
    __shared__ float s_cs[256];
    __shared__ float s_red[8];
    int t = threadIdx.x;
    int lane = t & 31, w = t >> 5;

    float cnt = g_scr[16384 + t];
    g_scr[16384 + t] = 0.f;  // self-clean for next replay
    float ncs = cs_in[t] * 0.99f + 0.01f * cnt;

    // n = sum(new_cs)
    float v = ncs;
#pragma unroll
    for (int o = 16; o; o >>= 1) v += __shfl_xor_sync(0xffffffffu, v, o);
    if (lane == 0) s_red[w] = v;
    __syncthreads();
    float nsum = 0.f;
#pragma unroll
    for (int j = 0; j < 8; j++) nsum += s_red[j];

    float csf = (ncs + 1e-5f) / (nsum + 256.f * 1e-5f) * nsum;
    s_cs[t] = csf;
    dout[OFF_CS + t] = csf;

    // perplexity
    float avg = cnt * (1.0f / (float)NVEC);
    float term = avg * logf(avg + 1e-10f);
    float e = term;
#pragma unroll
    for (int o = 16; o; o >>= 1) e += __shfl_xor_sync(0xffffffffu, e, o);
    __syncthreads();  // protect s_red reuse
    if (lane == 0) s_red[w] = e;
    __syncthreads();
    if (t == 0) {
        float es = 0.f;
        for (int j = 0; j < 8; j++) es += s_red[j];
        dout[OFF_PERP] = expf(-es);
        dout[OFF_LOSS] = 0.25f * g_scr[16640] * (1.0f / 8388608.0f);
        g_scr[16640] = 0.f;
    }

    // new_ema_w and new_emb_w; zero dw scratch after reading (same thread).
    for (int i = t; i < 16384; i += 256) {
        float ew = emaw_in[i] * 0.99f + 0.01f * g_scr[i];
        g_scr[i] = 0.f;
        dout[OFF_EMAW + i] = ew;
        dout[OFF_EMBW + i] = ew / s_cs[i >> 6];
    }
}

// ---------------------------------------------------------------------------
extern "C" void kernel_launch(void* const* d_in, const int* in_sizes, int n_in,
                              void* d_out, int out_size) {
    const float* in   = (const float*)d_in[0];
    const float* emb  = (const float*)d_in[1];
    const float* cs   = (const float*)d_in[2];
    const float* emaw = (const float*)d_in[3];
    float* dout = (float*)d_out;

    const int smem = 49936 * 4;  // 199744 B dynamic shared
    cudaFuncSetAttribute(vq_main, cudaFuncAttributeMaxDynamicSharedMemorySize, smem);

    // 4 launches/call: ncu's fixed -s 5 -c 1 (global launch #6) => vq_main.
    vq_pad<<<1, 32>>>();
    vq_main<<<NBLK, NTHR, smem>>>(in, emb, dout);
    vq_finalize<<<1, 256>>>(cs, emaw, dout);
    vq_pad<<<1, 32>>>();
}

// round 9
// speedup vs baseline: 2.3795x; 1.2317x over previous
#include <cuda_runtime.h>
#include <cuda_bf16.h>
#include <math.h>

#define NVEC 131072
#define KCODES 256
#define NBLK 148
#define NTHR 256
#define NWARP 8
#define TOTWARP (NBLK * NWARP)
#define NBATCH (NVEC / 32)

// Output packing (tuple flattened, fp32):
// loss(1), out(32*64*64*64), perplexity(1), idx(131072), new_emb_w(16384), new_cs(256), new_ema_w(16384)
#define OFF_LOSS 0
#define OFF_OUT  1
#define OFF_PERP 8388609
#define OFF_IDX  8388610
#define OFF_EMBW 8519682
#define OFF_CS   8536066
#define OFF_EMAW 8536322

// scratch: [0,16384) dw, [16384,16640) counts, [16640] loss accumulator
// Zero at module load; vq_finalize re-zeros after consuming => every graph
// replay (and the correctness call) sees zeros.
__device__ float g_scr[16641];
__device__ float g_pad_sink;

__global__ void vq_pad() { if (threadIdx.x == 0) g_pad_sink = 0.f; }

__device__ __forceinline__ unsigned packbf(float hi, float lo) {
    unsigned r;
    asm("cvt.rn.bf16x2.f32 %0, %1, %2;" : "=r"(r) : "f"(hi), "f"(lo));
    return r;
}

__device__ __forceinline__ void mma16816(float* c, const unsigned* a,
                                         unsigned b0, unsigned b1) {
    asm volatile(
        "mma.sync.aligned.m16n8k16.row.col.f32.bf16.bf16.f32 "
        "{%0,%1,%2,%3}, {%4,%5,%6,%7}, {%8,%9}, {%0,%1,%2,%3};"
        : "+f"(c[0]), "+f"(c[1]), "+f"(c[2]), "+f"(c[3])
        : "r"(a[0]), "r"(a[1]), "r"(a[2]), "r"(a[3]), "r"(b0), "r"(b1));
}

// ---------------------------------------------------------------------------
// Kernel 1: MMA distances (3-term bf16 split) + argmin + ST output + loss
//           + dw/count partials. One warp per batch of 32 vectors.
// ---------------------------------------------------------------------------
__global__ void __launch_bounds__(NTHR, 1)
vq_main(const float* __restrict__ in, const float* __restrict__ emb,
        float* __restrict__ dout) {
    extern __shared__ float sm[];
    float* s_eg  = sm;              // 16384: fp32 codebook, rotation-swizzled
    float* s_dw  = sm + 16384;      // 16640: dw accumulator, padded stride 65
    float* s_h   = sm + 33024;      // 256:   0.5*||e_k||^2
    float* s_cnt = sm + 33280;      // 256:   per-block counts
    float* s_red = sm + 33536;      // 8:     loss reduction
    __nv_bfloat16* s_eh = (__nv_bfloat16*)(sm + 33552);  // 256 x 72 bf16 hi
    __nv_bfloat16* s_el = (__nv_bfloat16*)(sm + 42768);  // 256 x 72 bf16 lo

    const int tid  = threadIdx.x;
    const int lane = tid & 31;

    for (int i = tid; i < 16640; i += NTHR) s_dw[i] = 0.f;
    for (int i = tid; i < 16384; i += NTHR) {
        float v = emb[i];
        int k = i >> 6, c = i & 63;
        s_eg[(k << 6) + ((c + k) & 63)] = v;
        __nv_bfloat16 hb = __float2bfloat16(v);
        s_eh[k * 72 + c] = hb;
        s_el[k * 72 + c] = __float2bfloat16(v - __bfloat162float(hb));
    }
    if (tid < KCODES) {
        float s = 0.f;
        const float* er = emb + (tid << 6);
#pragma unroll
        for (int c = 0; c < 64; c++) s += er[c] * er[c];
        s_h[tid] = 0.5f * s;
        s_cnt[tid] = 0.f;
    }
    __syncthreads();

    float lossacc = 0.f;
    const int gwarp = blockIdx.x * NWARP + (tid >> 5);

#pragma unroll 1
    for (int bat = gwarp; bat < NBATCH; bat += TOTWARP) {
        const int n0 = bat << 5;                       // 32 consecutive vectors
        const float* base = in + (n0 >> 12) * 262144 + (n0 & 4095);

        // -- A fragments straight from gmem: xh/xl bf16x2, m16n8k16 layout.
        // reg idx = (m*4+s)*4 + p*2 + q : rows m*16 + l/4 + q*8,
        // cols s*16 + (l%4)*2 + p*8 (+0,+1). All indices compile-time.
        unsigned xh[32], xl[32];
#pragma unroll
        for (int m = 0; m < 2; m++)
#pragma unroll
            for (int s = 0; s < 4; s++)
#pragma unroll
                for (int p = 0; p < 2; p++)
#pragma unroll
                    for (int q = 0; q < 2; q++) {
                        int rr = m * 16 + (lane >> 2) + q * 8;
                        int cc = s * 16 + (lane & 3) * 2 + p * 8;
                        float f0 = base[cc * 4096 + rr];
                        float f1 = base[(cc + 1) * 4096 + rr];
                        float h0 = __bfloat162float(__float2bfloat16(f0));
                        float h1 = __bfloat162float(__float2bfloat16(f1));
                        int ix = (m * 4 + s) * 4 + p * 2 + q;
                        xh[ix] = packbf(h1, h0);
                        xl[ix] = packbf(f1 - h1, f0 - h0);
                    }

        // -- Running argmin state: slot j covers row l/4 + j*8 (j=0..3).
        float best[4]  = {3.4e38f, 3.4e38f, 3.4e38f, 3.4e38f};
        float best2[4] = {3.4e38f, 3.4e38f, 3.4e38f, 3.4e38f};
        int   bk[4]    = {0, 0, 0, 0};

#pragma unroll 1
        for (int t = 0; t < 32; t++) {                 // 32 n-tiles of 8 codes
            float c[8] = {0.f, 0.f, 0.f, 0.f, 0.f, 0.f, 0.f, 0.f};
            const int erow = (t << 3) + (lane >> 2);
#pragma unroll
            for (int s = 0; s < 4; s++) {
                int koff = s * 16 + (lane & 3) * 2;
                unsigned bh0 = *(const unsigned*)&s_eh[erow * 72 + koff];
                unsigned bh1 = *(const unsigned*)&s_eh[erow * 72 + koff + 8];
                unsigned bl0 = *(const unsigned*)&s_el[erow * 72 + koff];
                unsigned bl1 = *(const unsigned*)&s_el[erow * 72 + koff + 8];
                mma16816(c,     &xh[s * 4],       bh0, bh1);   // Xh.Eh m0
                mma16816(c + 4, &xh[(4 + s) * 4], bh0, bh1);   // Xh.Eh m1
                mma16816(c,     &xh[s * 4],       bl0, bl1);   // Xh.El m0
                mma16816(c + 4, &xh[(4 + s) * 4], bl0, bl1);   // Xh.El m1
                mma16816(c,     &xl[s * 4],       bh0, bh1);   // Xl.Eh m0
                mma16816(c + 4, &xl[(4 + s) * 4], bh0, bh1);   // Xl.Eh m1
            }
            // scores: sc = 0.5||e||^2 - x.e ; cols n0t+(l%4)*2, +1
            int nb = (t << 3) + (lane & 3) * 2;
            float h0 = s_h[nb], h1 = s_h[nb + 1];
#pragma unroll
            for (int j = 0; j < 4; j++) {
                float s0 = h0 - c[2 * j], s1 = h1 - c[2 * j + 1];
                if (s0 < best[j]) { best2[j] = best[j]; best[j] = s0; bk[j] = nb; }
                else if (s0 < best2[j]) best2[j] = s0;
                if (s1 < best[j]) { best2[j] = best[j]; best[j] = s1; bk[j] = nb + 1; }
                else if (s1 < best2[j]) best2[j] = s1;
            }
        }

        // -- Quad reduce (lanes 4q..4q+3 share rows; disjoint col sets).
#pragma unroll
        for (int o = 1; o <= 2; o <<= 1)
#pragma unroll
            for (int j = 0; j < 4; j++) {
                float ob  = __shfl_xor_sync(0xffffffffu, best[j], o);
                float ob2 = __shfl_xor_sync(0xffffffffu, best2[j], o);
                int   ok  = __shfl_xor_sync(0xffffffffu, bk[j], o);
                float nb2 = fminf(fmaxf(best[j], ob), fminf(best2[j], ob2));
                if (ob < best[j] || (ob == best[j] && ok < bk[j])) bk[j] = ok;
                best[j] = fminf(best[j], ob);
                best2[j] = nb2;
            }

        // -- Redistribute: lane r owns row r = vector n0+r.
        // row r lives in quad r&7, slot r>>3.
        int src = (lane & 7) << 2, slot = lane >> 3;
        float bb = 0.f, bb2 = 0.f; int bbk = 0;
#pragma unroll
        for (int j = 0; j < 4; j++) {
            float tb  = __shfl_sync(0xffffffffu, best[j], src);
            float tb2 = __shfl_sync(0xffffffffu, best2[j], src);
            int   tk  = __shfl_sync(0xffffffffu, bk[j], src);
            if (slot == j) { bb = tb; bb2 = tb2; bbk = tk; }
        }

        // -- Near-tie rescue: MMA score noise ~1e-4; band 6e-3 (60x margin).
        // Evidence (R2): gap density ~0.4/unit => ~300 rescues chip-wide.
        unsigned fmask = __ballot_sync(0xffffffffu, (bb2 - bb) < 6e-3f);
        while (fmask) {
            int fs = __ffs(fmask) - 1; fmask &= fmask - 1;
            const float* xs = base + fs;
            double bd = 1e300; int bkk = 0;
#pragma unroll 1
            for (int kk = 0; kk < 8; kk++) {
                int k = kk * 32 + lane;
                const float* er = s_eg + (k << 6);
                double sA = 0.0, sB = 0.0;
#pragma unroll
                for (int cc = 0; cc < 64; cc += 2) {
                    double d0 = (double)xs[cc << 12] - (double)er[(cc + k) & 63];
                    double d1 = (double)xs[(cc + 1) << 12] - (double)er[(cc + 1 + k) & 63];
                    sA += d0 * d0; sB += d1 * d1;
                }
                double s = sA + sB;
                if (s < bd - 3e-6 || (s < bd + 3e-6 && k < bkk)) { bd = s; bkk = k; }
            }
#pragma unroll
            for (int o = 16; o; o >>= 1) {
                double od = __shfl_xor_sync(0xffffffffu, bd, o);
                int ok = __shfl_xor_sync(0xffffffffu, bkk, o);
                if (od < bd - 3e-6 || (od < bd + 3e-6 && ok < bkk)) { bd = od; bkk = ok; }
            }
            if (lane == fs) bbk = bkk;
        }

        // -- Epilogue: ST output fl(x + fl(q-x)), loss, dw/count.
        // Lane r = vector n0+r: all gmem accesses warp-coalesced per c.
        float* op = dout + OFF_OUT + (n0 >> 12) * 262144 + (n0 & 4095) + lane;
        const float* xpv = base + lane;
        int kb64 = bbk << 6;
        float* dwrow = s_dw + bbk * 65;   // bank=(bbk+c)%32: distinct codes, distinct banks
#pragma unroll
        for (int cc = 0; cc < 64; cc++) {
            float xv = xpv[cc << 12];
            float e = s_eg[kb64 + ((cc + bbk) & 63)];
            float df = e - xv;
            lossacc += df * df;
            op[cc << 12] = xv + df;
            atomicAdd(dwrow + cc, xv);
        }
        dout[OFF_IDX + n0 + lane] = (float)bbk;
        atomicAdd(s_cnt + bbk, 1.0f);
    }
    __syncthreads();

    // Flush per-block partials (padded -> logical layout) to global scratch.
    for (int i = tid; i < 16384; i += NTHR)
        atomicAdd(&g_scr[i], s_dw[(i >> 6) * 65 + (i & 63)]);
    if (tid < KCODES) atomicAdd(&g_scr[16384 + tid], s_cnt[tid]);

    // Loss: warp reduce -> shared -> one atomic per block.
#pragma unroll
    for (int o = 16; o; o >>= 1) lossacc += __shfl_xor_sync(0xffffffffu, lossacc, o);
    if (lane == 0) s_red[tid >> 5] = lossacc;
    __syncthreads();
    if (tid == 0) {
        float s = 0.f;
        for (int w = 0; w < NWARP; w++) s += s_red[w];
        atomicAdd(&g_scr[16640], s);
    }
}

// ---------------------------------------------------------------------------
// Kernel 2: finalize EMA updates, perplexity, loss; re-zero scratch.
// ---------------------------------------------------------------------------
__global__ void vq_finalize(const float* __restrict__ cs_in,
                            const float* __restrict__ emaw_in,
                            float* __restrict__ dout) {
    __shared__ float s_cs[256];
    __shared__ float s_red[8];
    int t = threadIdx.x;
    int lane = t & 31, w = t >> 5;

    float cnt = g_scr[16384 + t];
    g_scr[16384 + t] = 0.f;  // self-clean for next replay
    float ncs = cs_in[t] * 0.99f + 0.01f * cnt;

    float v = ncs;
#pragma unroll
    for (int o = 16; o; o >>= 1) v += __shfl_xor_sync(0xffffffffu, v, o);
    if (lane == 0) s_red[w] = v;
    __syncthreads();
    float nsum = 0.f;
#pragma unroll
    for (int j = 0; j < 8; j++) nsum += s_red[j];

    float csf = (ncs + 1e-5f) / (nsum + 256.f * 1e-5f) * nsum;
    s_cs[t] = csf;
    dout[OFF_CS + t] = csf;

    float avg = cnt * (1.0f / (float)NVEC);
    float e = avg * logf(avg + 1e-10f);
#pragma unroll
    for (int o = 16; o; o >>= 1) e += __shfl_xor_sync(0xffffffffu, e, o);
    __syncthreads();
    if (lane == 0) s_red[w] = e;
    __syncthreads();
    if (t == 0) {
        float es = 0.f;
        for (int j = 0; j < 8; j++) es += s_red[j];
        dout[OFF_PERP] = expf(-es);
        dout[OFF_LOSS] = 0.25f * g_scr[16640] * (1.0f / 8388608.0f);
        g_scr[16640] = 0.f;
    }

    for (int i = t; i < 16384; i += 256) {
        float ew = emaw_in[i] * 0.99f + 0.01f * g_scr[i];
        g_scr[i] = 0.f;
        dout[OFF_EMAW + i] = ew;
        dout[OFF_EMBW + i] = ew / s_cs[i >> 6];
    }
}

// ---------------------------------------------------------------------------
extern "C" void kernel_launch(void* const* d_in, const int* in_sizes, int n_in,
                              void* d_out, int out_size) {
    const float* in   = (const float*)d_in[0];
    const float* emb  = (const float*)d_in[1];
    const float* cs   = (const float*)d_in[2];
    const float* emaw = (const float*)d_in[3];
    float* dout = (float*)d_out;

    // floats: 33552 fp32 region + (2*9216) bf16-as-float region = 51984
    const int smem = 51984 * 4;  // 207936 B dynamic shared
    cudaFuncSetAttribute(vq_main, cudaFuncAttributeMaxDynamicSharedMemorySize, smem);

    // Period-3 launch pattern with vq_main at position 1: the observed ncu
    // capture index satisfies G = 4 mod 12 => G lands on vq_main.
    vq_main<<<NBLK, NTHR, smem>>>(in, emb, dout);
    vq_finalize<<<1, 256>>>(cs, emaw, dout);
    vq_pad<<<1, 32>>>();
}

// round 10
// speedup vs baseline: 2.4965x; 1.0491x over previous
#include <cuda_runtime.h>
#include <cuda_bf16.h>
#include <math.h>

#define NVEC 131072
#define KCODES 256
#define NBLK 148
#define NTHR 512
#define NWARP 16
#define TOTWARP (NBLK * NWARP)
#define NBATCH (NVEC / 16)

// Output packing (tuple flattened, fp32):
// loss(1), out(32*64*64*64), perplexity(1), idx(131072), new_emb_w(16384), new_cs(256), new_ema_w(16384)
#define OFF_LOSS 0
#define OFF_OUT  1
#define OFF_PERP 8388609
#define OFF_IDX  8388610
#define OFF_EMBW 8519682
#define OFF_CS   8536066
#define OFF_EMAW 8536322

// scratch: [0,16384) dw, [16384,16640) counts, [16640] loss accumulator
// Zero at module load; vq_finalize re-zeros after consuming => every graph
// replay (and the correctness call) sees zeros.
__device__ float g_scr[16641];
__device__ float g_pad_sink;

__global__ void vq_pad() { if (threadIdx.x == 0) g_pad_sink = 0.f; }

__device__ __forceinline__ unsigned packbf(float hi, float lo) {
    unsigned r;
    asm("cvt.rn.bf16x2.f32 %0, %1, %2;" : "=r"(r) : "f"(hi), "f"(lo));
    return r;
}

__device__ __forceinline__ void mma16816(float* c, const unsigned* a,
                                         unsigned b0, unsigned b1) {
    asm volatile(
        "mma.sync.aligned.m16n8k16.row.col.f32.bf16.bf16.f32 "
        "{%0,%1,%2,%3}, {%4,%5,%6,%7}, {%8,%9}, {%0,%1,%2,%3};"
        : "+f"(c[0]), "+f"(c[1]), "+f"(c[2]), "+f"(c[3])
        : "r"(a[0]), "r"(a[1]), "r"(a[2]), "r"(a[3]), "r"(b0), "r"(b1));
}

// ---------------------------------------------------------------------------
// Kernel 1: MMA distances (2-term bf16: xh.(eh+el); error xl.e sigma~0.013,
// rescued by fp64 within band 0.10) + argmin + ST output + loss + dw/count.
// One warp per batch of 16 vectors (M=16 -> small fragments -> 128-reg cap
// -> 16 warps/SM).
// ---------------------------------------------------------------------------
__global__ void __launch_bounds__(NTHR, 1)
vq_main(const float* __restrict__ in, const float* __restrict__ emb,
        float* __restrict__ dout) {
    extern __shared__ float sm[];
    float* s_eg  = sm;              // 16384: fp32 codebook, rotation-swizzled
    float* s_dw  = sm + 16384;      // 16640: dw accumulator, padded stride 65
    float* s_h   = sm + 33024;      // 256:   0.5*||e_k||^2
    float* s_cnt = sm + 33280;      // 256:   per-block counts
    float* s_red = sm + 33536;      // 16:    loss reduction
    __nv_bfloat16* s_eh = (__nv_bfloat16*)(sm + 33552);  // 256 x 72 bf16 hi
    __nv_bfloat16* s_el = (__nv_bfloat16*)(sm + 42768);  // 256 x 72 bf16 lo

    const int tid  = threadIdx.x;
    const int lane = tid & 31;

    for (int i = tid; i < 16640; i += NTHR) s_dw[i] = 0.f;
    for (int i = tid; i < 16384; i += NTHR) {
        float v = emb[i];
        int k = i >> 6, c = i & 63;
        s_eg[(k << 6) + ((c + k) & 63)] = v;
        __nv_bfloat16 hb = __float2bfloat16(v);
        s_eh[k * 72 + c] = hb;
        s_el[k * 72 + c] = __float2bfloat16(v - __bfloat162float(hb));
    }
    if (tid < KCODES) {
        float s = 0.f;
        const float* er = emb + (tid << 6);
#pragma unroll
        for (int c = 0; c < 64; c++) s += er[c] * er[c];
        s_h[tid] = 0.5f * s;
        s_cnt[tid] = 0.f;
    }
    __syncthreads();

    float lossacc = 0.f;
    const int gwarp = blockIdx.x * NWARP + (tid >> 5);

#pragma unroll 1
    for (int bat = gwarp; bat < NBATCH; bat += TOTWARP) {
        const int n0 = bat << 4;                       // 16 consecutive vectors
        const float* base = in + (n0 >> 12) * 262144 + (n0 & 4095);

        // -- A fragments (xh only) from gmem: rows l/4 + 8q, cols
        // s*16 + (l%4)*2 + 8p (+0,+1). Per-instruction: 4 cols x 8 consecutive
        // rows => 4 full 32B sectors. All indices compile-time.
        unsigned xh[16];
#pragma unroll
        for (int s = 0; s < 4; s++)
#pragma unroll
            for (int p = 0; p < 2; p++)
#pragma unroll
                for (int q = 0; q < 2; q++) {
                    int rr = (lane >> 2) + q * 8;
                    int cc = s * 16 + (lane & 3) * 2 + p * 8;
                    float f0 = base[cc * 4096 + rr];
                    float f1 = base[(cc + 1) * 4096 + rr];
                    xh[s * 4 + p * 2 + q] =
                        packbf(__bfloat162float(__float2bfloat16(f1)),
                               __bfloat162float(__float2bfloat16(f0)));
                }

        // -- Running argmin: slot j covers row (l/4) + 8j, j=0..1.
        float best[2]  = {3.4e38f, 3.4e38f};
        float best2[2] = {3.4e38f, 3.4e38f};
        int   bk[2]    = {0, 0};

#pragma unroll 1
        for (int t = 0; t < 32; t++) {                 // 32 n-tiles of 8 codes
            float c[4] = {0.f, 0.f, 0.f, 0.f};
            const int erow = (t << 3) + (lane >> 2);
#pragma unroll
            for (int s = 0; s < 4; s++) {
                int koff = s * 16 + (lane & 3) * 2;
                unsigned bh0 = *(const unsigned*)&s_eh[erow * 72 + koff];
                unsigned bh1 = *(const unsigned*)&s_eh[erow * 72 + koff + 8];
                unsigned bl0 = *(const unsigned*)&s_el[erow * 72 + koff];
                unsigned bl1 = *(const unsigned*)&s_el[erow * 72 + koff + 8];
                mma16816(c, &xh[s * 4], bh0, bh1);     // Xh.Eh
                mma16816(c, &xh[s * 4], bl0, bl1);     // Xh.El
            }
            // scores: sc = 0.5||e||^2 - x.e ; cols t*8 + (l%4)*2, +1
            int nb = (t << 3) + (lane & 3) * 2;
            float h0 = s_h[nb], h1 = s_h[nb + 1];
#pragma unroll
            for (int j = 0; j < 2; j++) {
                float s0 = h0 - c[2 * j], s1 = h1 - c[2 * j + 1];
                if (s0 < best[j]) { best2[j] = best[j]; best[j] = s0; bk[j] = nb; }
                else if (s0 < best2[j]) best2[j] = s0;
                if (s1 < best[j]) { best2[j] = best[j]; best[j] = s1; bk[j] = nb + 1; }
                else if (s1 < best2[j]) best2[j] = s1;
            }
        }

        // -- Quad reduce (lanes 4q..4q+3 share rows; disjoint col sets).
#pragma unroll
        for (int o = 1; o <= 2; o <<= 1)
#pragma unroll
            for (int j = 0; j < 2; j++) {
                float ob  = __shfl_xor_sync(0xffffffffu, best[j], o);
                float ob2 = __shfl_xor_sync(0xffffffffu, best2[j], o);
                int   ok  = __shfl_xor_sync(0xffffffffu, bk[j], o);
                float nb2 = fminf(fmaxf(best[j], ob), fminf(best2[j], ob2));
                if (ob < best[j] || (ob == best[j] && ok < bk[j])) bk[j] = ok;
                best[j] = fminf(best[j], ob);
                best2[j] = nb2;
            }

        // -- Redistribute: lane pair (2v, 2v+1) owns vector n0+v.
        // row v lives in quad v&7, slot v>>3.
        int v = lane >> 1;
        int src = (v & 7) << 2, slot = v >> 3;
        float bb = 0.f, bb2 = 0.f; int bbk = 0;
#pragma unroll
        for (int j = 0; j < 2; j++) {
            float tb  = __shfl_sync(0xffffffffu, best[j], src);
            float tb2 = __shfl_sync(0xffffffffu, best2[j], src);
            int   tk  = __shfl_sync(0xffffffffu, bk[j], src);
            if (slot == j) { bb = tb; bb2 = tb2; bbk = tk; }
        }

        // -- Near-tie rescue: 2-term noise sigma~0.013 => band 0.10 (~5.5
        // sigma of pairwise diff). ~5K rescues chip-wide (fp64 pipe, ~3us).
        unsigned fmask = __ballot_sync(0xffffffffu,
                                       (bb2 - bb) < 0.10f && (lane & 1) == 0);
        while (fmask) {
            int fs = __ffs(fmask) - 1; fmask &= fmask - 1;
            int vf = fs >> 1;
            const float* xs = base + vf;
            double bd = 1e300; int bkk = 0;
#pragma unroll 1
            for (int kk = 0; kk < 8; kk++) {
                int k = kk * 32 + lane;
                const float* er = s_eg + (k << 6);
                double sA = 0.0, sB = 0.0;
#pragma unroll
                for (int cc = 0; cc < 64; cc += 2) {
                    double d0 = (double)xs[cc << 12] - (double)er[(cc + k) & 63];
                    double d1 = (double)xs[(cc + 1) << 12] - (double)er[(cc + 1 + k) & 63];
                    sA += d0 * d0; sB += d1 * d1;
                }
                double s = sA + sB;
                if (s < bd - 3e-6 || (s < bd + 3e-6 && k < bkk)) { bd = s; bkk = k; }
            }
#pragma unroll
            for (int o = 16; o; o >>= 1) {
                double od = __shfl_xor_sync(0xffffffffu, bd, o);
                int ok = __shfl_xor_sync(0xffffffffu, bkk, o);
                if (od < bd - 3e-6 || (od < bd + 3e-6 && ok < bkk)) { bd = od; bkk = ok; }
            }
            if (v == vf) bbk = bkk;
        }

        // -- Epilogue: 2 lanes per vector (h = lane&1 -> channels 2d+h).
        // ST output fl(x + fl(q-x)) bit-faithfully, loss, dw/count.
        const int h = lane & 1;
        float* op = dout + OFF_OUT + (n0 >> 12) * 262144 + (n0 & 4095) + v;
        const float* xpv = base + v;
        int kb64 = bbk << 6;
        float* dwrow = s_dw + bbk * 65;   // bank=(bbk+c)%32
#pragma unroll
        for (int d = 0; d < 32; d++) {
            int cc = 2 * d + h;
            float xv = xpv[cc << 12];
            float e = s_eg[kb64 + ((cc + bbk) & 63)];
            float df = e - xv;
            lossacc += df * df;
            op[cc << 12] = xv + df;
            atomicAdd(dwrow + cc, xv);
        }
        if (h == 0) {
            dout[OFF_IDX + n0 + v] = (float)bbk;
            atomicAdd(s_cnt + bbk, 1.0f);
        }
    }
    __syncthreads();

    // Flush per-block partials (padded -> logical layout) to global scratch.
    for (int i = tid; i < 16384; i += NTHR)
        atomicAdd(&g_scr[i], s_dw[(i >> 6) * 65 + (i & 63)]);
    if (tid < KCODES) atomicAdd(&g_scr[16384 + tid], s_cnt[tid]);

    // Loss: warp reduce -> shared -> one atomic per block.
#pragma unroll
    for (int o = 16; o; o >>= 1) lossacc += __shfl_xor_sync(0xffffffffu, lossacc, o);
    if (lane == 0) s_red[tid >> 5] = lossacc;
    __syncthreads();
    if (tid == 0) {
        float s = 0.f;
        for (int w = 0; w < NWARP; w++) s += s_red[w];
        atomicAdd(&g_scr[16640], s);
    }
}

// ---------------------------------------------------------------------------
// Kernel 2: finalize EMA updates, perplexity, loss; re-zero scratch.
// ---------------------------------------------------------------------------
__global__ void vq_finalize(const float* __restrict__ cs_in,
                            const float* __restrict__ emaw_in,
                            float* __restrict__ dout) {
    __shared__ float s_cs[256];
    __shared__ float s_red[8];
    int t = threadIdx.x;
    int lane = t & 31, w = t >> 5;

    float cnt = g_scr[16384 + t];
    g_scr[16384 + t] = 0.f;  // self-clean for next replay
    float ncs = cs_in[t] * 0.99f + 0.01f * cnt;

    float v = ncs;
#pragma unroll
    for (int o = 16; o; o >>= 1) v += __shfl_xor_sync(0xffffffffu, v, o);
    if (lane == 0) s_red[w] = v;
    __syncthreads();
    float nsum = 0.f;
#pragma unroll
    for (int j = 0; j < 8; j++) nsum += s_red[j];

    float csf = (ncs + 1e-5f) / (nsum + 256.f * 1e-5f) * nsum;
    s_cs[t] = csf;
    dout[OFF_CS + t] = csf;

    float avg = cnt * (1.0f / (float)NVEC);
    float e = avg * logf(avg + 1e-10f);
#pragma unroll
    for (int o = 16; o; o >>= 1) e += __shfl_xor_sync(0xffffffffu, e, o);
    __syncthreads();
    if (lane == 0) s_red[w] = e;
    __syncthreads();
    if (t == 0) {
        float es = 0.f;
        for (int j = 0; j < 8; j++) es += s_red[j];
        dout[OFF_PERP] = expf(-es);
        dout[OFF_LOSS] = 0.25f * g_scr[16640] * (1.0f / 8388608.0f);
        g_scr[16640] = 0.f;
    }

    for (int i = t; i < 16384; i += 256) {
        float ew = emaw_in[i] * 0.99f + 0.01f * g_scr[i];
        g_scr[i] = 0.f;
        dout[OFF_EMAW + i] = ew;
        dout[OFF_EMBW + i] = ew / s_cs[i >> 6];
    }
}

// ---------------------------------------------------------------------------
extern "C" void kernel_launch(void* const* d_in, const int* in_sizes, int n_in,
                              void* d_out, int out_size) {
    const float* in   = (const float*)d_in[0];
    const float* emb  = (const float*)d_in[1];
    const float* cs   = (const float*)d_in[2];
    const float* emaw = (const float*)d_in[3];
    float* dout = (float*)d_out;

    // floats: 33552 fp32 region + 2*9216 bf16-pair region = 51984
    const int smem = 51984 * 4;  // 207936 B dynamic shared
    cudaFuncSetAttribute(vq_main, cudaFuncAttributeMaxDynamicSharedMemorySize, smem);

    // Period-3 launch pattern, vq_main at pos 1: ncu's capture index
    // (G = 4 mod 12) lands on vq_main (verified R9).
    vq_main<<<NBLK, NTHR, smem>>>(in, emb, dout);
    vq_finalize<<<1, 256>>>(cs, emaw, dout);
    vq_pad<<<1, 32>>>();
}

// round 12
// speedup vs baseline: 2.5253x; 1.0115x over previous
#include <cuda_runtime.h>
#include <cuda_bf16.h>
#include <math.h>

#define NVEC 131072
#define KCODES 256
#define NBLK 148
#define NTHR 512
#define NWARP 16
#define TOTWARP (NBLK * NWARP)
#define NBATCH (NVEC / 16)

// Output packing (tuple flattened, fp32):
// loss(1), out(32*64*64*64), perplexity(1), idx(131072), new_emb_w(16384), new_cs(256), new_ema_w(16384)
#define OFF_LOSS 0
#define OFF_OUT  1
#define OFF_PERP 8388609
#define OFF_IDX  8388610
#define OFF_EMBW 8519682
#define OFF_CS   8536066
#define OFF_EMAW 8536322

// Rescue band: 0.1 score units * 4096 (quant) * 256 (index pack) + slack.
#define BAND_KEYS 110000

// scratch: [0,16384) dw, [16384,16640) counts, [16640] loss accumulator
// Zero at module load; vq_finalize re-zeros after consuming.
__device__ float g_scr[16641];
__device__ float g_pad_sink;

__global__ void vq_pad() { if (threadIdx.x == 0) g_pad_sink = 0.f; }

__device__ __forceinline__ unsigned packbf(float hi, float lo) {
    unsigned r;
    asm("cvt.rn.bf16x2.f32 %0, %1, %2;" : "=r"(r) : "f"(hi), "f"(lo));
    return r;
}

__device__ __forceinline__ void mma16816(float* c, const unsigned* a,
                                         unsigned b0, unsigned b1) {
    asm volatile(
        "mma.sync.aligned.m16n8k16.row.col.f32.bf16.bf16.f32 "
        "{%0,%1,%2,%3}, {%4,%5,%6,%7}, {%8,%9}, {%0,%1,%2,%3};"
        : "+f"(c[0]), "+f"(c[1]), "+f"(c[2]), "+f"(c[3])
        : "r"(a[0]), "r"(a[1]), "r"(a[2]), "r"(a[3]), "r"(b0), "r"(b1));
}

// ---------------------------------------------------------------------------
// Kernel 1: MMA distances (2-term bf16: xh.(eh+el); error xl.e rescued by
// fp64 within key-band) + integer-key argmin + ST output + loss + dw/count.
// One warp per batch of 16 vectors.
// ---------------------------------------------------------------------------
__global__ void __launch_bounds__(NTHR, 1)
vq_main(const float* __restrict__ in, const float* __restrict__ emb,
        float* __restrict__ dout) {
    extern __shared__ float sm[];
    float* s_eg  = sm;              // 16384: fp32 codebook, rotation-swizzled
    float* s_dw  = sm + 16384;      // 16640: dw accumulator, padded stride 65
    float* s_h4  = sm + 33024;      // 256:   0.5*||e_k||^2 * 4096
    float* s_cnt = sm + 33280;      // 256:   per-block counts
    float* s_red = sm + 33536;      // 16:    loss reduction
    // Packed B operands: per (code row, s, quad q) one 8B word holding the 4
    // halves {e[s16+2q], e[s16+2q+1], e[s16+2q+8], e[s16+2q+9]}. Row stride
    // 80 halves => LDS.64 bank = 8*(row%4) + 2*q : conflict-free.
    __nv_bfloat16* s_eh = (__nv_bfloat16*)(sm + 33552);  // 256 x 80 halves
    __nv_bfloat16* s_el = (__nv_bfloat16*)(sm + 43792);  // 256 x 80 halves

    const int tid  = threadIdx.x;
    const int lane = tid & 31;

    for (int i = tid; i < 16640; i += NTHR) s_dw[i] = 0.f;
    for (int i = tid; i < 16384; i += NTHR) {
        float v = emb[i];
        int k = i >> 6, c = i & 63;
        s_eg[(k << 6) + ((c + k) & 63)] = v;
        __nv_bfloat16 hb = __float2bfloat16(v);
        int s = c >> 4, cp = c & 15;
        int q   = (cp < 8) ? (cp >> 1) : ((cp - 8) >> 1);
        int pos = (cp < 8) ? (cp & 1) : (2 + (cp & 1));
        int ad = k * 80 + s * 16 + q * 4 + pos;
        s_eh[ad] = hb;
        s_el[ad] = __float2bfloat16(v - __bfloat162float(hb));
    }
    if (tid < KCODES) {
        float s = 0.f;
        const float* er = emb + (tid << 6);
#pragma unroll
        for (int c = 0; c < 64; c++) s += er[c] * er[c];
        s_h4[tid] = 0.5f * s * 4096.0f;
        s_cnt[tid] = 0.f;
    }
    __syncthreads();

    float lossacc = 0.f;
    const int gwarp = blockIdx.x * NWARP + (tid >> 5);

#pragma unroll 1
    for (int bat = gwarp; bat < NBATCH; bat += TOTWARP) {
        const int n0 = bat << 4;                       // 16 consecutive vectors
        const float* base = in + (n0 >> 12) * 262144 + (n0 & 4095);

        // -- A fragments (xh only): rows l/4 + 8q, cols s*16+(l%4)*2+8p.
        unsigned xh[16];
#pragma unroll
        for (int s = 0; s < 4; s++)
#pragma unroll
            for (int p = 0; p < 2; p++)
#pragma unroll
                for (int q = 0; q < 2; q++) {
                    int rr = (lane >> 2) + q * 8;
                    int cc = s * 16 + (lane & 3) * 2 + p * 8;
                    float f0 = base[cc * 4096 + rr];
                    float f1 = base[(cc + 1) * 4096 + rr];
                    xh[s * 4 + p * 2 + q] =
                        packbf(__bfloat162float(__float2bfloat16(f1)),
                               __bfloat162float(__float2bfloat16(f0)));
                }

        // -- Running argmin as integer keys: key = rn(4096*sc)*256 + code.
        // Lower key == lower score (tie -> lower code). slot j = row l/4+8j.
        int best[2]  = {0x7FFFFFFF, 0x7FFFFFFF};
        int best2[2] = {0x7FFFFFFF, 0x7FFFFFFF};

#pragma unroll 1
        for (int t = 0; t < 32; t++) {                 // 32 n-tiles of 8 codes
            // Two independent accumulator sets: MMA chain depth 4, not 8.
            float c0[4] = {0.f, 0.f, 0.f, 0.f};
            float c1[4] = {0.f, 0.f, 0.f, 0.f};
            const int ebase = ((t << 3) + (lane >> 2)) * 80 + (lane & 3) * 4;
#pragma unroll
            for (int s = 0; s < 4; s++) {
                uint2 bh = *(const uint2*)(s_eh + ebase + s * 16);
                uint2 bl = *(const uint2*)(s_el + ebase + s * 16);
                float* cc = (s < 2) ? c0 : c1;
                mma16816(cc, &xh[s * 4], bh.x, bh.y);   // Xh.Eh
                mma16816(cc, &xh[s * 4], bl.x, bl.y);   // Xh.El
            }
            int nb = (t << 3) + (lane & 3) * 2;
            float h0 = s_h4[nb], h1 = s_h4[nb + 1];
#pragma unroll
            for (int j = 0; j < 2; j++) {
                int k0 = __float2int_rn(fmaf(c0[2 * j] + c1[2 * j],
                                             -4096.f, h0)) * 256 + nb;
                int k1 = __float2int_rn(fmaf(c0[2 * j + 1] + c1[2 * j + 1],
                                             -4096.f, h1)) * 256 + nb + 1;
                int kmin = min(k0, k1), kmax = max(k0, k1);
                best2[j] = min(min(best2[j], kmax), max(best[j], kmin));
                best[j]  = min(best[j], kmin);
            }
        }

        // -- Quad reduce (lanes 4q..4q+3 share rows; disjoint code sets).
#pragma unroll
        for (int o = 1; o <= 2; o <<= 1)
#pragma unroll
            for (int j = 0; j < 2; j++) {
                int ob  = __shfl_xor_sync(0xffffffffu, best[j], o);
                int ob2 = __shfl_xor_sync(0xffffffffu, best2[j], o);
                best2[j] = min(min(best2[j], ob2), max(best[j], ob));
                best[j]  = min(best[j], ob);
            }

        // -- Redistribute: lane pair (2v,2v+1) owns vector n0+v.
        int v = lane >> 1;
        int src = (v & 7) << 2, slot = v >> 3;
        int bb = 0, bb2 = 0;
#pragma unroll
        for (int j = 0; j < 2; j++) {
            int tb  = __shfl_sync(0xffffffffu, best[j], src);
            int tb2 = __shfl_sync(0xffffffffu, best2[j], src);
            if (slot == j) { bb = tb; bb2 = tb2; }
        }
        int bbk = bb & 255;

        // -- Near-tie rescue (fp64 exact), ~5K rescues chip-wide.
        unsigned fmask = __ballot_sync(0xffffffffu,
                                       (bb2 - bb) < BAND_KEYS && (lane & 1) == 0);
        while (fmask) {
            int fs = __ffs(fmask) - 1; fmask &= fmask - 1;
            int vf = fs >> 1;
            const float* xs = base + vf;
            double bd = 1e300; int bkk = 0;
#pragma unroll 1
            for (int kk = 0; kk < 8; kk++) {
                int k = kk * 32 + lane;
                const float* er = s_eg + (k << 6);
                double sA = 0.0, sB = 0.0;
#pragma unroll
                for (int cc = 0; cc < 64; cc += 2) {
                    double d0 = (double)xs[cc << 12] - (double)er[(cc + k) & 63];
                    double d1 = (double)xs[(cc + 1) << 12] - (double)er[(cc + 1 + k) & 63];
                    sA += d0 * d0; sB += d1 * d1;
                }
                double s = sA + sB;
                if (s < bd - 3e-6 || (s < bd + 3e-6 && k < bkk)) { bd = s; bkk = k; }
            }
#pragma unroll
            for (int o = 16; o; o >>= 1) {
                double od = __shfl_xor_sync(0xffffffffu, bd, o);
                int ok = __shfl_xor_sync(0xffffffffu, bkk, o);
                if (od < bd - 3e-6 || (od < bd + 3e-6 && ok < bkk)) { bd = od; bkk = ok; }
            }
            if (v == vf) bbk = bkk;
        }

        // -- Epilogue: 2 lanes per vector (h = lane&1 -> channels 2d+h).
        const int h = lane & 1;
        float* op = dout + OFF_OUT + (n0 >> 12) * 262144 + (n0 & 4095) + v;
        const float* xpv = base + v;
        int kb64 = bbk << 6;
        float* dwrow = s_dw + bbk * 65;   // bank=(bbk+c)%32
#pragma unroll
        for (int d = 0; d < 32; d++) {
            int cc = 2 * d + h;
            float xv = xpv[cc << 12];
            float e = s_eg[kb64 + ((cc + bbk) & 63)];
            float df = e - xv;
            lossacc += df * df;
            op[cc << 12] = xv + df;
            atomicAdd(dwrow + cc, xv);
        }
        if (h == 0) {
            dout[OFF_IDX + n0 + v] = (float)bbk;
            atomicAdd(s_cnt + bbk, 1.0f);
        }
    }
    __syncthreads();

    // Flush per-block partials (padded -> logical layout) to global scratch.
    for (int i = tid; i < 16384; i += NTHR)
        atomicAdd(&g_scr[i], s_dw[(i >> 6) * 65 + (i & 63)]);
    if (tid < KCODES) atomicAdd(&g_scr[16384 + tid], s_cnt[tid]);

    // Loss: warp reduce -> shared -> one atomic per block.
#pragma unroll
    for (int o = 16; o; o >>= 1) lossacc += __shfl_xor_sync(0xffffffffu, lossacc, o);
    if (lane == 0) s_red[tid >> 5] = lossacc;
    __syncthreads();
    if (tid == 0) {
        float s = 0.f;
        for (int w = 0; w < NWARP; w++) s += s_red[w];
        atomicAdd(&g_scr[16640], s);
    }
}

// ---------------------------------------------------------------------------
// Kernel 2: finalize EMA updates, perplexity, loss; re-zero scratch.
// ---------------------------------------------------------------------------
__global__ void vq_finalize(const float* __restrict__ cs_in,
                            const float* __restrict__ emaw_in,
                            float* __restrict__ dout) {
    __shared__ float s_cs[256];
    __shared__ float s_red[8];
    int t = threadIdx.x;
    int lane = t & 31, w = t >> 5;

    float cnt = g_scr[16384 + t];
    g_scr[16384 + t] = 0.f;  // self-clean for next replay
    float ncs = cs_in[t] * 0.99f + 0.01f * cnt;

    float v = ncs;
#pragma unroll
    for (int o = 16; o; o >>= 1) v += __shfl_xor_sync(0xffffffffu, v, o);
    if (lane == 0) s_red[w] = v;
    __syncthreads();
    float nsum = 0.f;
#pragma unroll
    for (int j = 0; j < 8; j++) nsum += s_red[j];

    float csf = (ncs + 1e-5f) / (nsum + 256.f * 1e-5f) * nsum;
    s_cs[t] = csf;
    dout[OFF_CS + t] = csf;

    float avg = cnt * (1.0f / (float)NVEC);
    float e = avg * logf(avg + 1e-10f);
#pragma unroll
    for (int o = 16; o; o >>= 1) e += __shfl_xor_sync(0xffffffffu, e, o);
    __syncthreads();
    if (lane == 0) s_red[w] = e;
    __syncthreads();
    if (t == 0) {
        float es = 0.f;
        for (int j = 0; j < 8; j++) es += s_red[j];
        dout[OFF_PERP] = expf(-es);
        dout[OFF_LOSS] = 0.25f * g_scr[16640] * (1.0f / 8388608.0f);
        g_scr[16640] = 0.f;
    }

    for (int i = t; i < 16384; i += 256) {
        float ew = emaw_in[i] * 0.99f + 0.01f * g_scr[i];
        g_scr[i] = 0.f;
        dout[OFF_EMAW + i] = ew;
        dout[OFF_EMBW + i] = ew / s_cs[i >> 6];
    }
}

// ---------------------------------------------------------------------------
extern "C" void kernel_launch(void* const* d_in, const int* in_sizes, int n_in,
                              void* d_out, int out_size) {
    const float* in   = (const float*)d_in[0];
    const float* emb  = (const float*)d_in[1];
    const float* cs   = (const float*)d_in[2];
    const float* emaw = (const float*)d_in[3];
    float* dout = (float*)d_out;

    // floats: 33552 fp32 region + 2 * (256*80/2 = 10240) bf16 region = 54032
    const int smem = 54032 * 4;  // 216128 B dynamic shared
    cudaFuncSetAttribute(vq_main, cudaFuncAttributeMaxDynamicSharedMemorySize, smem);

    // Period-3 launch pattern, vq_main at pos 1: ncu capture (G = 4 mod 12)
    // lands on vq_main (verified R9/R10).
    vq_main<<<NBLK, NTHR, smem>>>(in, emb, dout);
    vq_finalize<<<1, 256>>>(cs, emaw, dout);
    vq_pad<<<1, 32>>>();
}